// round 2
// baseline (speedup 1.0000x reference)
#include <cuda_runtime.h>
#include <math.h>

// ---------------------------------------------------------------------------
// Problem constants
// ---------------------------------------------------------------------------
namespace {
constexpr int B_FULL  = 2048;
constexpr int N_PIX   = 1024;
constexpr int M_FEAT  = 4;
constexpr int T_DIV   = 64;
constexpr int R_RANK  = 128;
constexpr int C_CLS   = 10;
constexpr int PER_DIV = 16;
constexpr int K_DIM   = R_RANK * M_FEAT;   // 512: k = i*4 + m (matches w_mid memory order)

constexpr int BT      = 64;    // batch rows per block
constexpr int NTHR    = 256;
constexpr int KC      = 32;    // k-chunk staged through smem
constexpr int NCHUNK  = K_DIM / KC;        // 16

constexpr int SS_PAD  = 132;   // padded row stride for state tile (bank-conflict relief)
constexpr int SP_PAD  = 33;    // padded row stride for S' tile

// dynamic smem layout (floats)
constexpr int OFF_SS  = 0;                          // BT * SS_PAD
constexpr int OFF_SP  = OFF_SS + BT * SS_PAD;       // BT * SP_PAD
constexpr int OFF_SW  = OFF_SP + BT * SP_PAD;       // KC * R_RANK
constexpr int OFF_SX  = OFF_SW + KC * R_RANK;       // BT * M_FEAT
constexpr int OFF_WL  = OFF_SX + BT * M_FEAT;       // R_RANK
constexpr int SMEM_FLOATS = OFF_WL + R_RANK;
constexpr int SMEM_BYTES  = SMEM_FLOATS * (int)sizeof(float);
}

// ---------------------------------------------------------------------------
// Device scratch (no allocations allowed in kernel_launch)
// ---------------------------------------------------------------------------
__device__ float4 g_div4[T_DIV * B_FULL];         // [t][b] -> float4 of M=4 features
__device__ float  g_logits[B_FULL * C_CLS];       // [b][c]

// ---------------------------------------------------------------------------
// Kernel 1: feature map + division averaging
//   div[t][b][m] = mean over 16 pixels of phi(x),  phi = (c^3, c^2 s, c s^2, s^3)
// ---------------------------------------------------------------------------
__global__ void feat_kernel(const float* __restrict__ tensor) {
    int idx = blockIdx.x * blockDim.x + threadIdx.x;       // 131072 = B_FULL * T_DIV
    if (idx >= B_FULL * T_DIV) return;
    int b = idx >> 6;
    int t = idx & (T_DIV - 1);

    const float4* p = reinterpret_cast<const float4*>(tensor + b * N_PIX + t * PER_DIV);
    float a0 = 0.f, a1 = 0.f, a2 = 0.f, a3 = 0.f;
#pragma unroll
    for (int j = 0; j < 4; ++j) {
        float4 v = p[j];
        float xs[4] = {v.x, v.y, v.z, v.w};
#pragma unroll
        for (int q = 0; q < 4; ++q) {
            float ang = 1.57079632679489662f * xs[q];
            float s, c;
            sincosf(ang, &s, &c);
            float c2 = c * c, s2 = s * s;
            a0 += c2 * c;
            a1 += c2 * s;
            a2 += c * s2;
            a3 += s2 * s;
        }
    }
    const float inv = 1.0f / (float)PER_DIV;
    g_div4[t * B_FULL + b] = make_float4(a0 * inv, a1 * inv, a2 * inv, a3 * inv);
}

// ---------------------------------------------------------------------------
// Kernel 2: TT recurrence.  One block = (class c, 64-row batch tile).
// Per step: new_s = S' @ W_flat,  S'[b, i*4+m] = s[b,i]*x[b,m],
//           W_flat = contiguous (512,128) slice of w_mid[c].
// Tiled fp32 GEMM: K staged through smem in KC=32 chunks with register
// prefetch; 4x8 register tile per thread (256 threads cover 64x128).
// ---------------------------------------------------------------------------
__global__ __launch_bounds__(NTHR) void rec_kernel(const float* __restrict__ w_first,
                                                   const float* __restrict__ w_mid,
                                                   const float* __restrict__ w_last) {
    extern __shared__ float smem[];
    float* sS  = smem + OFF_SS;    // [BT][SS_PAD] current state
    float* sSp = smem + OFF_SP;    // [BT][SP_PAD] S' chunk
    float* sW  = smem + OFF_SW;    // [KC][R_RANK] W chunk
    float* sX  = smem + OFF_SX;    // [BT][4]      x_t
    float* sWl = smem + OFF_WL;    // [R_RANK]     last-kernel projection

    const int c     = blockIdx.y;
    const int b0    = blockIdx.x * BT;
    const int tid   = threadIdx.x;
    const int tx    = tid & 15;    // column group: cols tx*8 .. tx*8+7
    const int ty    = tid >> 4;    // row group: rows ty*4 .. ty*4+3

    const float* Wc = w_mid + c * (K_DIM * R_RANK);

    // ---- init: state[b][o] = sum_m w_first[c,0,m,o]  (same for every b) ----
    if (tid < R_RANK) {
        const float* wf = w_first + c * (M_FEAT * R_RANK);
        float v = wf[tid] + wf[R_RANK + tid] + wf[2 * R_RANK + tid] + wf[3 * R_RANK + tid];
        for (int b = 0; b < BT; ++b) sS[b * SS_PAD + tid] = v;
        const float* wl = w_last + c * (R_RANK * M_FEAT);
        sWl[tid] = wl[tid * 4] + wl[tid * 4 + 1] + wl[tid * 4 + 2] + wl[tid * 4 + 3];
    }

    const float* gdiv = reinterpret_cast<const float*>(g_div4);

    for (int t = 0; t < T_DIV; ++t) {
        // load x_t for this tile: 256 consecutive floats
        sX[tid] = gdiv[(t * B_FULL + b0) * M_FEAT + tid];

        float acc[4][8];
#pragma unroll
        for (int r = 0; r < 4; ++r)
#pragma unroll
            for (int q = 0; q < 8; ++q) acc[r][q] = 0.f;

        // prefetch chunk 0 into registers
        float4 pre[4];
        {
            const float4* src = reinterpret_cast<const float4*>(Wc);
#pragma unroll
            for (int j = 0; j < 4; ++j) pre[j] = src[tid + j * NTHR];
        }

        for (int kc = 0; kc < NCHUNK; ++kc) {
            __syncthreads();  // prev chunk consumers done; sS/sX writes visible (kc==0)

            // stage W chunk into smem
            {
                float4* dst = reinterpret_cast<float4*>(sW);
#pragma unroll
                for (int j = 0; j < 4; ++j) dst[tid + j * NTHR] = pre[j];
            }
            // build S' chunk: 2048 elems, 8 per thread
            {
                int bb  = tid >> 2;
                int kkb = (tid & 3) * 8;
                float xv[4] = {sX[bb * 4 + 0], sX[bb * 4 + 1],
                               sX[bb * 4 + 2], sX[bb * 4 + 3]};
#pragma unroll
                for (int u = 0; u < 8; ++u) {
                    int k = kc * KC + kkb + u;
                    sSp[bb * SP_PAD + kkb + u] = sS[bb * SS_PAD + (k >> 2)] * xv[k & 3];
                }
            }
            // prefetch next chunk (L2 latency hidden behind this chunk's FMAs)
            if (kc + 1 < NCHUNK) {
                const float4* src = reinterpret_cast<const float4*>(Wc + (kc + 1) * KC * R_RANK);
#pragma unroll
                for (int j = 0; j < 4; ++j) pre[j] = src[tid + j * NTHR];
            }
            __syncthreads();

            // compute: 32 k-iterations, 32 FMAs each
#pragma unroll 8
            for (int kk = 0; kk < KC; ++kk) {
                float4 w0 = *reinterpret_cast<const float4*>(&sW[kk * R_RANK + tx * 8]);
                float4 w1 = *reinterpret_cast<const float4*>(&sW[kk * R_RANK + tx * 8 + 4]);
#pragma unroll
                for (int r = 0; r < 4; ++r) {
                    float a = sSp[(ty * 4 + r) * SP_PAD + kk];
                    acc[r][0] += a * w0.x; acc[r][1] += a * w0.y;
                    acc[r][2] += a * w0.z; acc[r][3] += a * w0.w;
                    acc[r][4] += a * w1.x; acc[r][5] += a * w1.y;
                    acc[r][6] += a * w1.z; acc[r][7] += a * w1.w;
                }
            }
        }

        __syncthreads();  // all S' builds (sS reads) done -> safe to overwrite state
#pragma unroll
        for (int r = 0; r < 4; ++r) {
            float* dst = &sS[(ty * 4 + r) * SS_PAD + tx * 8];
            *reinterpret_cast<float4*>(dst)     = make_float4(acc[r][0], acc[r][1], acc[r][2], acc[r][3]);
            *reinterpret_cast<float4*>(dst + 4) = make_float4(acc[r][4], acc[r][5], acc[r][6], acc[r][7]);
        }
    }

    __syncthreads();
    // final projection: logits[b] = dot(state[b], sWl)
    if (tid < BT) {
        float sum = 0.f;
#pragma unroll 8
        for (int i = 0; i < R_RANK; ++i) sum += sS[tid * SS_PAD + i] * sWl[i];
        g_logits[(b0 + tid) * C_CLS + c] = sum;
    }
}

// ---------------------------------------------------------------------------
// Kernel 3: log_softmax over C=10 classes per batch row
// ---------------------------------------------------------------------------
__global__ void lsm_kernel(float* __restrict__ out) {
    int b = blockIdx.x * blockDim.x + threadIdx.x;
    if (b >= B_FULL) return;
    float v[C_CLS];
    float mx = -INFINITY;
#pragma unroll
    for (int c = 0; c < C_CLS; ++c) {
        v[c] = g_logits[b * C_CLS + c];
        mx = fmaxf(mx, v[c]);
    }
    float s = 0.f;
#pragma unroll
    for (int c = 0; c < C_CLS; ++c) s += expf(v[c] - mx);
    float l = mx + logf(s);
#pragma unroll
    for (int c = 0; c < C_CLS; ++c) out[b * C_CLS + c] = v[c] - l;
}

// ---------------------------------------------------------------------------
// Entry point
// ---------------------------------------------------------------------------
extern "C" void kernel_launch(void* const* d_in, const int* in_sizes, int n_in,
                              void* d_out, int out_size) {
    const float* tensor  = (const float*)d_in[0];   // (2048, 1024)
    const float* w_first = (const float*)d_in[1];   // (10, 1, 4, 128)
    const float* w_mid   = (const float*)d_in[2];   // (10, 128, 4, 128)
    const float* w_last  = (const float*)d_in[3];   // (10, 128, 4, 1)
    float* out = (float*)d_out;                     // (2048, 10)

    cudaFuncSetAttribute(rec_kernel, cudaFuncAttributeMaxDynamicSharedMemorySize, SMEM_BYTES);

    feat_kernel<<<(B_FULL * T_DIV) / NTHR, NTHR>>>(tensor);
    rec_kernel<<<dim3(B_FULL / BT, C_CLS), NTHR, SMEM_BYTES>>>(w_first, w_mid, w_last);
    lsm_kernel<<<(B_FULL + NTHR - 1) / NTHR, NTHR>>>(out);
}

// round 5
// speedup vs baseline: 9.9480x; 9.9480x over previous
#include <cuda_runtime.h>
#include <cuda_bf16.h>
#include <math.h>
#include <cstdint>

// ---------------------------------------------------------------------------
// Problem constants
// ---------------------------------------------------------------------------
namespace {
constexpr int B_FULL  = 2048;
constexpr int N_PIX   = 1024;
constexpr int T_DIV   = 64;
constexpr int C_CLS   = 10;
constexpr int PER_DIV = 16;
constexpr int K_DIM   = 512;          // k = i*4 + m (w_mid memory order)
constexpr int R_RANK  = 128;
constexpr int BT      = 64;           // batch rows per CTA
constexpr int NTHR    = 128;          // 4 warps: 2(m) x 2(n), warp tile m32 x n64

constexpr int PADK    = 520;          // padded k-stride (halves) -> conflict-free ldmatrix

// smem byte offsets
constexpr int OFF_B   = 0;                         // [128][520] bf16 = 133120
constexpr int OFF_A   = OFF_B + R_RANK * PADK * 2; // [64][520] bf16 = 66560
constexpr int OFF_X   = OFF_A + BT * PADK * 2;     // 64 float4 = 1024
constexpr int OFF_S0  = OFF_X + 1024;              // 128 f32
constexpr int OFF_WL  = OFF_S0 + 512;              // 128 f32
constexpr int OFF_RED = OFF_WL + 512;              // 64*8 f32 = 2048
constexpr int SMEM_BYTES = OFF_RED + 2048;         // 203776
}

// ---------------------------------------------------------------------------
// Device scratch
// ---------------------------------------------------------------------------
__device__ float4 g_div4[T_DIV * B_FULL];      // [t][b] -> M=4 features
__device__ float  g_logits[B_FULL * C_CLS];    // [b][c]

// ---------------------------------------------------------------------------
// Small asm helpers (all base-sm_103 legal: ldmatrix sm_75+, mma bf16 sm_80+)
// ---------------------------------------------------------------------------
__device__ __forceinline__ uint32_t smem_to_u32(const void* p) {
    uint32_t a;
    asm("{ .reg .u64 t; cvta.to.shared.u64 t, %1; cvt.u32.u64 %0, t; }" : "=r"(a) : "l"(p));
    return a;
}
__device__ __forceinline__ void ldsm4(uint32_t* r, uint32_t addr) {
    asm volatile("ldmatrix.sync.aligned.m8n8.x4.shared.b16 {%0,%1,%2,%3}, [%4];"
                 : "=r"(r[0]), "=r"(r[1]), "=r"(r[2]), "=r"(r[3]) : "r"(addr));
}
__device__ __forceinline__ void mma16816(float* d, const uint32_t* a, uint32_t b0, uint32_t b1) {
    asm volatile("mma.sync.aligned.m16n8k16.row.col.f32.bf16.bf16.f32 "
                 "{%0,%1,%2,%3}, {%4,%5,%6,%7}, {%8,%9}, {%0,%1,%2,%3};"
                 : "+f"(d[0]), "+f"(d[1]), "+f"(d[2]), "+f"(d[3])
                 : "r"(a[0]), "r"(a[1]), "r"(a[2]), "r"(a[3]), "r"(b0), "r"(b1));
}
__device__ __forceinline__ uint32_t packbf(float hi, float lo) {
    uint32_t u;
    asm("cvt.rn.bf16x2.f32 %0, %1, %2;" : "=r"(u) : "f"(hi), "f"(lo));
    return u;   // memory order: [lo, hi]
}

// ---------------------------------------------------------------------------
// Kernel 1: feature map + division averaging
// ---------------------------------------------------------------------------
__global__ void feat_kernel(const float* __restrict__ tensor) {
    int idx = blockIdx.x * blockDim.x + threadIdx.x;
    if (idx >= B_FULL * T_DIV) return;
    int b = idx >> 6;
    int t = idx & (T_DIV - 1);
    const float4* p = reinterpret_cast<const float4*>(tensor + b * N_PIX + t * PER_DIV);
    float a0 = 0.f, a1 = 0.f, a2 = 0.f, a3 = 0.f;
#pragma unroll
    for (int j = 0; j < 4; ++j) {
        float4 v = p[j];
        float xs[4] = {v.x, v.y, v.z, v.w};
#pragma unroll
        for (int q = 0; q < 4; ++q) {
            float ang = 1.57079632679489662f * xs[q];
            float s, c;
            sincosf(ang, &s, &c);
            float c2 = c * c, s2 = s * s;
            a0 += c2 * c; a1 += c2 * s; a2 += c * s2; a3 += s2 * s;
        }
    }
    const float inv = 1.0f / (float)PER_DIV;
    g_div4[t * B_FULL + b] = make_float4(a0 * inv, a1 * inv, a2 * inv, a3 * inv);
}

// ---------------------------------------------------------------------------
// Kernel 2: TT recurrence via ldmatrix + mma.sync (bf16, fp32 accum).
// CTA = (class c, 64 batch rows). Warp tile m32 x n64 (warps: 2m x 2n).
// State = mma accumulator fragments. Per step: each warp converts its D
// fragments into the shared A operand A[b, 4i+m] = bf16(s_i * x_m), then a
// 64x128x512 bf16 GEMM against SMEM-resident weights B[o][k] rebuilds state.
// ---------------------------------------------------------------------------
__global__ __launch_bounds__(NTHR) void rec_hmma_kernel(const float* __restrict__ w_first,
                                                        const float* __restrict__ w_mid,
                                                        const float* __restrict__ w_last) {
    extern __shared__ char smem[];
    const int tid = threadIdx.x;
    const int l   = tid & 31;
    const int wid = tid >> 5;
    const int mg  = wid & 1;      // m-group: rows mg*32 .. mg*32+31
    const int ng  = wid >> 1;     // n-group: cols ng*64 .. ng*64+63
    const int c   = blockIdx.y;
    const int b0  = blockIdx.x * BT;

    const uint32_t smem_u = smem_to_u32(smem);
    __nv_bfloat16* sB = reinterpret_cast<__nv_bfloat16*>(smem + OFF_B);
    float*  s0s = reinterpret_cast<float*>(smem + OFF_S0);
    float*  wls = reinterpret_cast<float*>(smem + OFF_WL);
    float4* sX  = reinterpret_cast<float4*>(smem + OFF_X);
    float*  sRed = reinterpret_cast<float*>(smem + OFF_RED);

    // ---- stage weights: sB[o][k] = bf16(w_mid[c, k, o]), padded stride ----
    {
        const float* Wc = w_mid + c * (K_DIM * R_RANK);
        for (int q = tid; q < K_DIM * R_RANK / 4; q += NTHR) {
            int k = q >> 5;
            int j = (q & 31) << 2;
            float4 v = *reinterpret_cast<const float4*>(Wc + k * R_RANK + j);
            sB[(j + 0) * PADK + k] = __float2bfloat16(v.x);
            sB[(j + 1) * PADK + k] = __float2bfloat16(v.y);
            sB[(j + 2) * PADK + k] = __float2bfloat16(v.z);
            sB[(j + 3) * PADK + k] = __float2bfloat16(v.w);
        }
    }
    // ---- s0[o] = sum_m w_first[c,0,m,o]; wl[o] = sum_m w_last[c,o,m] ----
    {
        const float* wf = w_first + c * 512;
        s0s[tid] = wf[tid] + wf[128 + tid] + wf[256 + tid] + wf[384 + tid];
        const float* wl = w_last + c * 512;
        wls[tid] = wl[4 * tid] + wl[4 * tid + 1] + wl[4 * tid + 2] + wl[4 * tid + 3];
    }

    // ldmatrix address bases (bytes), canonical x4 lane->row mapping
    uint32_t aBase[2], bBase[4];
#pragma unroll
    for (int mt = 0; mt < 2; ++mt)
        aBase[mt] = smem_u + OFF_A +
            (((mg * 32 + mt * 16 + (l & 7) + ((l >> 3) & 1) * 8) * PADK + (l >> 4) * 8) << 1);
#pragma unroll
    for (int p = 0; p < 4; ++p)
        bBase[p] = smem_u + OFF_B +
            (((ng * 64 + p * 16 + (l >> 4) * 8 + (l & 7)) * PADK + ((l >> 3) & 1) * 8) << 1);

    float acc[2][8][4];
    const int g  = l >> 2;     // row within 8-group
    const int cc = l & 3;      // col pair selector

    for (int t = 0; t < T_DIV; ++t) {
        if (tid < BT) sX[tid] = g_div4[t * B_FULL + b0 + tid];
        __syncthreads();   // sX ready; previous step's mma done reading sA

        if (t == 0) {
            // A[b, 4i+m] = bf16(s0[i] * x[b][m]); thread owns i = tid
            float s = s0s[tid];
            for (int b = 0; b < BT; ++b) {
                float4 x = sX[b];
                uint2 u;
                u.x = packbf(s * x.y, s * x.x);
                u.y = packbf(s * x.w, s * x.z);
                *reinterpret_cast<uint2*>(smem + OFF_A + ((b * PADK + 4 * tid) << 1)) = u;
            }
        } else {
            // convert this warp's D fragments into A
#pragma unroll
            for (int mt = 0; mt < 2; ++mt) {
                int r = mg * 32 + mt * 16 + g;
                float4 xa = sX[r];
                float4 xb = sX[r + 8];
#pragma unroll
                for (int nt = 0; nt < 8; ++nt) {
                    int i0 = ng * 64 + nt * 8 + 2 * cc;
                    float c0 = acc[mt][nt][0], c1 = acc[mt][nt][1];
                    float c2 = acc[mt][nt][2], c3 = acc[mt][nt][3];
                    uint4 ua, ub;
                    ua.x = packbf(c0 * xa.y, c0 * xa.x);
                    ua.y = packbf(c0 * xa.w, c0 * xa.z);
                    ua.z = packbf(c1 * xa.y, c1 * xa.x);
                    ua.w = packbf(c1 * xa.w, c1 * xa.z);
                    *reinterpret_cast<uint4*>(smem + OFF_A + ((r * PADK + 4 * i0) << 1)) = ua;
                    ub.x = packbf(c2 * xb.y, c2 * xb.x);
                    ub.y = packbf(c2 * xb.w, c2 * xb.z);
                    ub.z = packbf(c3 * xb.y, c3 * xb.x);
                    ub.w = packbf(c3 * xb.w, c3 * xb.z);
                    *reinterpret_cast<uint4*>(smem + OFF_A + (((r + 8) * PADK + 4 * i0) << 1)) = ub;
                }
            }
        }
#pragma unroll
        for (int mt = 0; mt < 2; ++mt)
#pragma unroll
            for (int nt = 0; nt < 8; ++nt)
#pragma unroll
                for (int q = 0; q < 4; ++q) acc[mt][nt][q] = 0.f;
        __syncthreads();   // sA fully built

        // GEMM: 32 k-tiles of 16
#pragma unroll 2
        for (int kt = 0; kt < 32; ++kt) {
            uint32_t A0[4], A1[4], Bf[4][4];
            ldsm4(A0, aBase[0] + kt * 32);
            ldsm4(A1, aBase[1] + kt * 32);
#pragma unroll
            for (int p = 0; p < 4; ++p) ldsm4(Bf[p], bBase[p] + kt * 32);
#pragma unroll
            for (int nt = 0; nt < 8; ++nt) {
                uint32_t b0v = Bf[nt >> 1][(nt & 1) * 2];
                uint32_t b1v = Bf[nt >> 1][(nt & 1) * 2 + 1];
                mma16816(acc[0][nt], A0, b0v, b1v);
                mma16816(acc[1][nt], A1, b0v, b1v);
            }
        }
    }

    // ---- final projection: logits[b] = dot(state_b, wl) ----
#pragma unroll
    for (int mt = 0; mt < 2; ++mt) {
        int r = mg * 32 + mt * 16 + g;
        float p0 = 0.f, p1 = 0.f;
#pragma unroll
        for (int nt = 0; nt < 8; ++nt) {
            int i0 = ng * 64 + nt * 8 + 2 * cc;
            float w0 = wls[i0], w1 = wls[i0 + 1];
            p0 += acc[mt][nt][0] * w0 + acc[mt][nt][1] * w1;
            p1 += acc[mt][nt][2] * w0 + acc[mt][nt][3] * w1;
        }
        sRed[r * 8 + ng * 4 + cc]       = p0;
        sRed[(r + 8) * 8 + ng * 4 + cc] = p1;
    }
    __syncthreads();
    if (tid < BT) {
        float sum = 0.f;
#pragma unroll
        for (int q = 0; q < 8; ++q) sum += sRed[tid * 8 + q];
        g_logits[(b0 + tid) * C_CLS + c] = sum;
    }
}

// ---------------------------------------------------------------------------
// Kernel 3: log_softmax over C=10
// ---------------------------------------------------------------------------
__global__ void lsm_kernel(float* __restrict__ out) {
    int b = blockIdx.x * blockDim.x + threadIdx.x;
    if (b >= B_FULL) return;
    float v[C_CLS];
    float mx = -INFINITY;
#pragma unroll
    for (int c = 0; c < C_CLS; ++c) {
        v[c] = g_logits[b * C_CLS + c];
        mx = fmaxf(mx, v[c]);
    }
    float s = 0.f;
#pragma unroll
    for (int c = 0; c < C_CLS; ++c) s += expf(v[c] - mx);
    float lg = mx + logf(s);
#pragma unroll
    for (int c = 0; c < C_CLS; ++c) out[b * C_CLS + c] = v[c] - lg;
}

// ---------------------------------------------------------------------------
// Entry point
// ---------------------------------------------------------------------------
extern "C" void kernel_launch(void* const* d_in, const int* in_sizes, int n_in,
                              void* d_out, int out_size) {
    const float* tensor  = (const float*)d_in[0];   // (2048, 1024)
    const float* w_first = (const float*)d_in[1];   // (10, 1, 4, 128)
    const float* w_mid   = (const float*)d_in[2];   // (10, 128, 4, 128)
    const float* w_last  = (const float*)d_in[3];   // (10, 128, 4, 1)
    float* out = (float*)d_out;                     // (2048, 10)

    cudaFuncSetAttribute(rec_hmma_kernel, cudaFuncAttributeMaxDynamicSharedMemorySize, SMEM_BYTES);

    feat_kernel<<<(B_FULL * T_DIV) / 256, 256>>>(tensor);
    rec_hmma_kernel<<<dim3(B_FULL / BT, C_CLS), NTHR, SMEM_BYTES>>>(w_first, w_mid, w_last);
    lsm_kernel<<<(B_FULL + 255) / 256, 256>>>(out);
}

// round 7
// speedup vs baseline: 12.0062x; 1.2069x over previous
#include <cuda_runtime.h>
#include <cuda_bf16.h>
#include <math.h>
#include <cstdint>

// ---------------------------------------------------------------------------
// Problem constants
// ---------------------------------------------------------------------------
namespace {
constexpr int B_FULL  = 2048;
constexpr int N_PIX   = 1024;
constexpr int T_DIV   = 64;
constexpr int C_CLS   = 10;
constexpr int PER_DIV = 16;
constexpr int K_DIM   = 512;          // k = i*4 + m (w_mid memory order)
constexpr int R_RANK  = 128;
constexpr int BT      = 64;           // batch rows per CTA
constexpr int NTHR    = 256;          // 8 warps: 2(m) x 4(n), warp tile m32 x n32

constexpr int PADK    = 520;          // padded k-stride (halves) -> conflict-free ldmatrix

// smem byte offsets
constexpr int OFF_B   = 0;                         // [128][520] bf16 = 133120
constexpr int OFF_A   = OFF_B + R_RANK * PADK * 2; // [64][520] bf16 = 66560
constexpr int OFF_X   = OFF_A + BT * PADK * 2;     // 64 float4 = 1024
constexpr int OFF_S0  = OFF_X + 1024;              // 128 f32
constexpr int OFF_WL  = OFF_S0 + 512;              // 128 f32
constexpr int OFF_RED = OFF_WL + 512;              // 64*16 f32 = 4096
constexpr int SMEM_BYTES = OFF_RED + 4096;         // 205824
}

// ---------------------------------------------------------------------------
// Device scratch
// ---------------------------------------------------------------------------
__device__ float4 g_div4[T_DIV * B_FULL];      // [t][b] -> M=4 features
__device__ float  g_logits[B_FULL * C_CLS];    // [b][c]

// ---------------------------------------------------------------------------
// asm helpers (base-sm_103 legal: ldmatrix sm_75+, mma bf16 sm_80+)
// ---------------------------------------------------------------------------
__device__ __forceinline__ uint32_t smem_to_u32(const void* p) {
    uint32_t a;
    asm("{ .reg .u64 t; cvta.to.shared.u64 t, %1; cvt.u32.u64 %0, t; }" : "=r"(a) : "l"(p));
    return a;
}
__device__ __forceinline__ void ldsm4(uint32_t* r, uint32_t addr) {
    asm volatile("ldmatrix.sync.aligned.m8n8.x4.shared.b16 {%0,%1,%2,%3}, [%4];"
                 : "=r"(r[0]), "=r"(r[1]), "=r"(r[2]), "=r"(r[3]) : "r"(addr));
}
__device__ __forceinline__ void mma16816(float* d, const uint32_t* a, uint32_t b0, uint32_t b1) {
    asm volatile("mma.sync.aligned.m16n8k16.row.col.f32.bf16.bf16.f32 "
                 "{%0,%1,%2,%3}, {%4,%5,%6,%7}, {%8,%9}, {%0,%1,%2,%3};"
                 : "+f"(d[0]), "+f"(d[1]), "+f"(d[2]), "+f"(d[3])
                 : "r"(a[0]), "r"(a[1]), "r"(a[2]), "r"(a[3]), "r"(b0), "r"(b1));
}
__device__ __forceinline__ uint32_t packbf(float hi, float lo) {
    uint32_t u;
    asm("cvt.rn.bf16x2.f32 %0, %1, %2;" : "=r"(u) : "f"(hi), "f"(lo));
    return u;   // memory order: [lo, hi]
}

// ---------------------------------------------------------------------------
// Kernel 1: feature map + division averaging
// ---------------------------------------------------------------------------
__global__ void feat_kernel(const float* __restrict__ tensor) {
    int idx = blockIdx.x * blockDim.x + threadIdx.x;
    if (idx >= B_FULL * T_DIV) return;
    int b = idx >> 6;
    int t = idx & (T_DIV - 1);
    const float4* p = reinterpret_cast<const float4*>(tensor + b * N_PIX + t * PER_DIV);
    float a0 = 0.f, a1 = 0.f, a2 = 0.f, a3 = 0.f;
#pragma unroll
    for (int j = 0; j < 4; ++j) {
        float4 v = p[j];
        float xs[4] = {v.x, v.y, v.z, v.w};
#pragma unroll
        for (int q = 0; q < 4; ++q) {
            float ang = 1.57079632679489662f * xs[q];
            float s, c;
            sincosf(ang, &s, &c);
            float c2 = c * c, s2 = s * s;
            a0 += c2 * c; a1 += c2 * s; a2 += c * s2; a3 += s2 * s;
        }
    }
    const float inv = 1.0f / (float)PER_DIV;
    g_div4[t * B_FULL + b] = make_float4(a0 * inv, a1 * inv, a2 * inv, a3 * inv);
}

// ---------------------------------------------------------------------------
// Kernel 2: TT recurrence via ldmatrix + mma.sync (bf16, fp32 accum).
// CTA = (class c, 64 batch rows). 8 warps, 2(m) x 4(n), warp tile m32 x n32.
// State = mma accumulator fragments. Per step: each warp converts its D
// fragments into the shared A operand A[b, 4i+m] = bf16(s_i * x_m), then a
// 64x128x512 bf16 GEMM against SMEM-resident weights B[o][k] rebuilds state.
// k-loop double-buffers ldmatrix fragments to overlap LDSM with HMMA.
// ---------------------------------------------------------------------------
__global__ __launch_bounds__(NTHR) void rec_hmma_kernel(const float* __restrict__ w_first,
                                                        const float* __restrict__ w_mid,
                                                        const float* __restrict__ w_last) {
    extern __shared__ char smem[];
    const int tid = threadIdx.x;
    const int l   = tid & 31;
    const int wid = tid >> 5;
    const int mg  = wid & 1;      // m-group: rows mg*32 .. mg*32+31
    const int ng  = wid >> 1;     // n-group: cols ng*32 .. ng*32+31 (0..3)
    const int c   = blockIdx.y;
    const int b0  = blockIdx.x * BT;

    const uint32_t smem_u = smem_to_u32(smem);
    __nv_bfloat16* sB = reinterpret_cast<__nv_bfloat16*>(smem + OFF_B);
    float*  s0s  = reinterpret_cast<float*>(smem + OFF_S0);
    float*  wls  = reinterpret_cast<float*>(smem + OFF_WL);
    float4* sX   = reinterpret_cast<float4*>(smem + OFF_X);
    float*  sRed = reinterpret_cast<float*>(smem + OFF_RED);

    // ---- stage weights: sB[o][k] = bf16(w_mid[c, k, o]), padded stride ----
    {
        const float* Wc = w_mid + c * (K_DIM * R_RANK);
        for (int q = tid; q < K_DIM * R_RANK / 4; q += NTHR) {
            int k = q >> 5;
            int j = (q & 31) << 2;
            float4 v = *reinterpret_cast<const float4*>(Wc + k * R_RANK + j);
            sB[(j + 0) * PADK + k] = __float2bfloat16(v.x);
            sB[(j + 1) * PADK + k] = __float2bfloat16(v.y);
            sB[(j + 2) * PADK + k] = __float2bfloat16(v.z);
            sB[(j + 3) * PADK + k] = __float2bfloat16(v.w);
        }
    }
    // ---- s0[o] = sum_m w_first[c,0,m,o]; wl[o] = sum_m w_last[c,o,m] ----
    if (tid < R_RANK) {
        const float* wf = w_first + c * 512;
        s0s[tid] = wf[tid] + wf[128 + tid] + wf[256 + tid] + wf[384 + tid];
        const float* wl = w_last + c * 512;
        wls[tid] = wl[4 * tid] + wl[4 * tid + 1] + wl[4 * tid + 2] + wl[4 * tid + 3];
    }
    __syncthreads();

    // ldmatrix address bases (bytes), canonical x4 lane->row mapping
    uint32_t aBase[2], bBase[2];
#pragma unroll
    for (int mt = 0; mt < 2; ++mt)
        aBase[mt] = smem_u + OFF_A +
            (((mg * 32 + mt * 16 + (l & 7) + ((l >> 3) & 1) * 8) * PADK + (l >> 4) * 8) << 1);
#pragma unroll
    for (int p = 0; p < 2; ++p)
        bBase[p] = smem_u + OFF_B +
            (((ng * 32 + p * 16 + (l >> 4) * 8 + (l & 7)) * PADK + ((l >> 3) & 1) * 8) << 1);

    float acc[2][4][4];
    const int g  = l >> 2;     // row within 8-group
    const int cc = l & 3;      // col pair selector

    for (int t = 0; t < T_DIV; ++t) {
        if (tid < BT) sX[tid] = g_div4[t * B_FULL + b0 + tid];
        __syncthreads();   // sX ready; previous step's mma done reading sA

        if (t == 0) {
            // A[b, 4i+m] = bf16(s0[i] * x[b][m]); thread owns i = tid&127,
            // half the rows per thread-half.
            int i  = tid & 127;
            int bh = tid >> 7;
            float s = s0s[i];
            for (int b = bh * 32; b < bh * 32 + 32; ++b) {
                float4 x = sX[b];
                uint2 u;
                u.x = packbf(s * x.y, s * x.x);
                u.y = packbf(s * x.w, s * x.z);
                *reinterpret_cast<uint2*>(smem + OFF_A + ((b * PADK + 4 * i) << 1)) = u;
            }
        } else {
            // convert this warp's D fragments into A
#pragma unroll
            for (int mt = 0; mt < 2; ++mt) {
                int r = mg * 32 + mt * 16 + g;
                float4 xa = sX[r];
                float4 xb = sX[r + 8];
#pragma unroll
                for (int nt = 0; nt < 4; ++nt) {
                    int i0 = ng * 32 + nt * 8 + 2 * cc;
                    float c0 = acc[mt][nt][0], c1 = acc[mt][nt][1];
                    float c2 = acc[mt][nt][2], c3 = acc[mt][nt][3];
                    uint4 ua, ub;
                    ua.x = packbf(c0 * xa.y, c0 * xa.x);
                    ua.y = packbf(c0 * xa.w, c0 * xa.z);
                    ua.z = packbf(c1 * xa.y, c1 * xa.x);
                    ua.w = packbf(c1 * xa.w, c1 * xa.z);
                    *reinterpret_cast<uint4*>(smem + OFF_A + ((r * PADK + 4 * i0) << 1)) = ua;
                    ub.x = packbf(c2 * xb.y, c2 * xb.x);
                    ub.y = packbf(c2 * xb.w, c2 * xb.z);
                    ub.z = packbf(c3 * xb.y, c3 * xb.x);
                    ub.w = packbf(c3 * xb.w, c3 * xb.z);
                    *reinterpret_cast<uint4*>(smem + OFF_A + (((r + 8) * PADK + 4 * i0) << 1)) = ub;
                }
            }
        }
#pragma unroll
        for (int mt = 0; mt < 2; ++mt)
#pragma unroll
            for (int nt = 0; nt < 4; ++nt)
#pragma unroll
                for (int q = 0; q < 4; ++q) acc[mt][nt][q] = 0.f;
        __syncthreads();   // sA fully built

        // GEMM: 32 k-tiles of 16, double-buffered fragments
        uint32_t Af[2][2][4], Bfr[2][2][4];
        ldsm4(Af[0][0], aBase[0]);
        ldsm4(Af[0][1], aBase[1]);
        ldsm4(Bfr[0][0], bBase[0]);
        ldsm4(Bfr[0][1], bBase[1]);
#pragma unroll 4
        for (int kt = 0; kt < 32; ++kt) {
            int cur = kt & 1, nx = cur ^ 1;
            if (kt < 31) {
                ldsm4(Af[nx][0], aBase[0] + (kt + 1) * 32);
                ldsm4(Af[nx][1], aBase[1] + (kt + 1) * 32);
                ldsm4(Bfr[nx][0], bBase[0] + (kt + 1) * 32);
                ldsm4(Bfr[nx][1], bBase[1] + (kt + 1) * 32);
            }
#pragma unroll
            for (int nt = 0; nt < 4; ++nt) {
                uint32_t b0v = Bfr[cur][nt >> 1][(nt & 1) * 2];
                uint32_t b1v = Bfr[cur][nt >> 1][(nt & 1) * 2 + 1];
                mma16816(acc[0][nt], Af[cur][0], b0v, b1v);
                mma16816(acc[1][nt], Af[cur][1], b0v, b1v);
            }
        }
    }

    // ---- final projection: logits[b] = dot(state_b, wl) ----
#pragma unroll
    for (int mt = 0; mt < 2; ++mt) {
        int r = mg * 32 + mt * 16 + g;
        float p0 = 0.f, p1 = 0.f;
#pragma unroll
        for (int nt = 0; nt < 4; ++nt) {
            int i0 = ng * 32 + nt * 8 + 2 * cc;
            float w0 = wls[i0], w1 = wls[i0 + 1];
            p0 += acc[mt][nt][0] * w0 + acc[mt][nt][1] * w1;
            p1 += acc[mt][nt][2] * w0 + acc[mt][nt][3] * w1;
        }
        sRed[r * 16 + ng * 4 + cc]       = p0;
        sRed[(r + 8) * 16 + ng * 4 + cc] = p1;
    }
    __syncthreads();
    if (tid < BT) {
        float sum = 0.f;
#pragma unroll
        for (int q = 0; q < 16; ++q) sum += sRed[tid * 16 + q];
        g_logits[(b0 + tid) * C_CLS + c] = sum;
    }
}

// ---------------------------------------------------------------------------
// Kernel 3: log_softmax over C=10
// ---------------------------------------------------------------------------
__global__ void lsm_kernel(float* __restrict__ out) {
    int b = blockIdx.x * blockDim.x + threadIdx.x;
    if (b >= B_FULL) return;
    float v[C_CLS];
    float mx = -INFINITY;
#pragma unroll
    for (int c = 0; c < C_CLS; ++c) {
        v[c] = g_logits[b * C_CLS + c];
        mx = fmaxf(mx, v[c]);
    }
    float s = 0.f;
#pragma unroll
    for (int c = 0; c < C_CLS; ++c) s += expf(v[c] - mx);
    float lg = mx + logf(s);
#pragma unroll
    for (int c = 0; c < C_CLS; ++c) out[b * C_CLS + c] = v[c] - lg;
}

// ---------------------------------------------------------------------------
// Entry point
// ---------------------------------------------------------------------------
extern "C" void kernel_launch(void* const* d_in, const int* in_sizes, int n_in,
                              void* d_out, int out_size) {
    const float* tensor  = (const float*)d_in[0];   // (2048, 1024)
    const float* w_first = (const float*)d_in[1];   // (10, 1, 4, 128)
    const float* w_mid   = (const float*)d_in[2];   // (10, 128, 4, 128)
    const float* w_last  = (const float*)d_in[3];   // (10, 128, 4, 1)
    float* out = (float*)d_out;                     // (2048, 10)

    cudaFuncSetAttribute(rec_hmma_kernel, cudaFuncAttributeMaxDynamicSharedMemorySize, SMEM_BYTES);

    feat_kernel<<<(B_FULL * T_DIV) / 256, 256>>>(tensor);
    rec_hmma_kernel<<<dim3(B_FULL / BT, C_CLS), NTHR, SMEM_BYTES>>>(w_first, w_mid, w_last);
    lsm_kernel<<<(B_FULL + 255) / 256, 256>>>(out);
}

// round 8
// speedup vs baseline: 12.4604x; 1.0378x over previous
#include <cuda_runtime.h>
#include <cuda_bf16.h>
#include <math.h>
#include <cstdint>

// ---------------------------------------------------------------------------
// Problem constants
// ---------------------------------------------------------------------------
namespace {
constexpr int B_FULL  = 2048;
constexpr int N_PIX   = 1024;
constexpr int T_DIV   = 64;
constexpr int C_CLS   = 10;
constexpr int PER_DIV = 16;
constexpr int K_DIM   = 512;          // k = i*4 + m (w_mid memory order)
constexpr int R_RANK  = 128;
constexpr int BT      = 64;           // batch rows per CTA
constexpr int NTHR    = 256;          // 8 warps: 2(m) x 4(n), warp tile m32 x n32
constexpr int NB      = 12;           // k-tiles whose B fragments persist in registers

constexpr int PADK    = 520;          // padded k-stride (halves) -> conflict-free ldmatrix

// smem byte offsets
constexpr int OFF_B   = 0;                         // [128][520] bf16 = 133120
constexpr int OFF_A   = OFF_B + R_RANK * PADK * 2; // [64][520] bf16 = 66560
constexpr int OFF_X   = OFF_A + BT * PADK * 2;     // 64 float4 = 1024
constexpr int OFF_S0  = OFF_X + 1024;              // 128 f32
constexpr int OFF_WL  = OFF_S0 + 512;              // 128 f32
constexpr int OFF_RED = OFF_WL + 512;              // 64*16 f32 = 4096
constexpr int SMEM_BYTES = OFF_RED + 4096;         // 205824
}

// ---------------------------------------------------------------------------
// Device scratch
// ---------------------------------------------------------------------------
__device__ float4 g_div4[T_DIV * B_FULL];      // [t][b] -> M=4 features
__device__ float  g_logits[B_FULL * C_CLS];    // [b][c]

// ---------------------------------------------------------------------------
// asm helpers (base-sm_103 legal)
// ---------------------------------------------------------------------------
__device__ __forceinline__ uint32_t smem_to_u32(const void* p) {
    uint32_t a;
    asm("{ .reg .u64 t; cvta.to.shared.u64 t, %1; cvt.u32.u64 %0, t; }" : "=r"(a) : "l"(p));
    return a;
}
__device__ __forceinline__ void ldsm4(uint32_t* r, uint32_t addr) {
    asm volatile("ldmatrix.sync.aligned.m8n8.x4.shared.b16 {%0,%1,%2,%3}, [%4];"
                 : "=r"(r[0]), "=r"(r[1]), "=r"(r[2]), "=r"(r[3]) : "r"(addr));
}
__device__ __forceinline__ void mma16816(float* d, const uint32_t* a, uint32_t b0, uint32_t b1) {
    asm volatile("mma.sync.aligned.m16n8k16.row.col.f32.bf16.bf16.f32 "
                 "{%0,%1,%2,%3}, {%4,%5,%6,%7}, {%8,%9}, {%0,%1,%2,%3};"
                 : "+f"(d[0]), "+f"(d[1]), "+f"(d[2]), "+f"(d[3])
                 : "r"(a[0]), "r"(a[1]), "r"(a[2]), "r"(a[3]), "r"(b0), "r"(b1));
}
__device__ __forceinline__ uint32_t packbf(float hi, float lo) {
    uint32_t u;
    asm("cvt.rn.bf16x2.f32 %0, %1, %2;" : "=r"(u) : "f"(hi), "f"(lo));
    return u;   // memory order: [lo, hi]
}
__device__ __forceinline__ uint32_t mulbf2(uint32_t a, uint32_t b) {
    uint32_t d;
    asm("mul.bf16x2 %0, %1, %2;" : "=r"(d) : "r"(a), "r"(b));
    return d;
}

// ---------------------------------------------------------------------------
// Kernel 1: feature map + division averaging
// ---------------------------------------------------------------------------
__global__ void feat_kernel(const float* __restrict__ tensor) {
    int idx = blockIdx.x * blockDim.x + threadIdx.x;
    if (idx >= B_FULL * T_DIV) return;
    int b = idx >> 6;
    int t = idx & (T_DIV - 1);
    const float4* p = reinterpret_cast<const float4*>(tensor + b * N_PIX + t * PER_DIV);
    float a0 = 0.f, a1 = 0.f, a2 = 0.f, a3 = 0.f;
#pragma unroll
    for (int j = 0; j < 4; ++j) {
        float4 v = p[j];
        float xs[4] = {v.x, v.y, v.z, v.w};
#pragma unroll
        for (int q = 0; q < 4; ++q) {
            float ang = 1.57079632679489662f * xs[q];
            float s, c;
            sincosf(ang, &s, &c);
            float c2 = c * c, s2 = s * s;
            a0 += c2 * c; a1 += c2 * s; a2 += c * s2; a3 += s2 * s;
        }
    }
    const float inv = 1.0f / (float)PER_DIV;
    g_div4[t * B_FULL + b] = make_float4(a0 * inv, a1 * inv, a2 * inv, a3 * inv);
}

// ---------------------------------------------------------------------------
// Kernel 2: TT recurrence via ldmatrix + mma.sync (bf16, fp32 accum).
// 8 warps 2(m) x 4(n), warp tile m32 x n32.
// New vs R7: B fragments for kt 0..NB-1 persist in registers across all 64
// steps (B is step-invariant); A-build uses bf16x2 HMUL2; x_t prefetched
// into registers during the GEMM.
// ---------------------------------------------------------------------------
__global__ __launch_bounds__(NTHR) void rec_hmma_kernel(const float* __restrict__ w_first,
                                                        const float* __restrict__ w_mid,
                                                        const float* __restrict__ w_last) {
    extern __shared__ char smem[];
    const int tid = threadIdx.x;
    const int l   = tid & 31;
    const int wid = tid >> 5;
    const int mg  = wid & 1;      // m-group: rows mg*32 .. mg*32+31
    const int ng  = wid >> 1;     // n-group: cols ng*32 .. ng*32+31 (0..3)
    const int c   = blockIdx.y;
    const int b0  = blockIdx.x * BT;

    const uint32_t smem_u = smem_to_u32(smem);
    __nv_bfloat16* sB = reinterpret_cast<__nv_bfloat16*>(smem + OFF_B);
    float*  s0s  = reinterpret_cast<float*>(smem + OFF_S0);
    float*  wls  = reinterpret_cast<float*>(smem + OFF_WL);
    float4* sX   = reinterpret_cast<float4*>(smem + OFF_X);
    float*  sRed = reinterpret_cast<float*>(smem + OFF_RED);

    // ---- stage weights: sB[o][k] = bf16(w_mid[c, k, o]), padded stride ----
    {
        const float* Wc = w_mid + c * (K_DIM * R_RANK);
        for (int q = tid; q < K_DIM * R_RANK / 4; q += NTHR) {
            int k = q >> 5;
            int j = (q & 31) << 2;
            float4 v = *reinterpret_cast<const float4*>(Wc + k * R_RANK + j);
            sB[(j + 0) * PADK + k] = __float2bfloat16(v.x);
            sB[(j + 1) * PADK + k] = __float2bfloat16(v.y);
            sB[(j + 2) * PADK + k] = __float2bfloat16(v.z);
            sB[(j + 3) * PADK + k] = __float2bfloat16(v.w);
        }
    }
    // ---- s0[o] = sum_m w_first[c,0,m,o]; wl[o] = sum_m w_last[c,o,m] ----
    if (tid < R_RANK) {
        const float* wf = w_first + c * 512;
        s0s[tid] = wf[tid] + wf[128 + tid] + wf[256 + tid] + wf[384 + tid];
        const float* wl = w_last + c * 512;
        wls[tid] = wl[4 * tid] + wl[4 * tid + 1] + wl[4 * tid + 2] + wl[4 * tid + 3];
    }
    __syncthreads();

    // ldmatrix address bases (bytes), canonical x4 lane->row mapping
    uint32_t aBase[2], bBase[2];
#pragma unroll
    for (int mt = 0; mt < 2; ++mt)
        aBase[mt] = smem_u + OFF_A +
            (((mg * 32 + mt * 16 + (l & 7) + ((l >> 3) & 1) * 8) * PADK + (l >> 4) * 8) << 1);
#pragma unroll
    for (int p = 0; p < 2; ++p)
        bBase[p] = smem_u + OFF_B +
            (((ng * 32 + p * 16 + (l >> 4) * 8 + (l & 7)) * PADK + ((l >> 3) & 1) * 8) << 1);

    // ---- persistent B fragments for kt 0..NB-1 (B is step-invariant) ----
    uint32_t Bp[NB][2][4];
#pragma unroll
    for (int kt = 0; kt < NB; ++kt) {
        ldsm4(Bp[kt][0], bBase[0] + kt * 32);
        ldsm4(Bp[kt][1], bBase[1] + kt * 32);
    }

    float acc[2][4][4];
    const int g  = l >> 2;     // row within 8-group
    const int cc = l & 3;      // col pair selector

    float4 gx = make_float4(0.f, 0.f, 0.f, 0.f);
    if (tid < BT) gx = g_div4[b0 + tid];   // t = 0

    for (int t = 0; t < T_DIV; ++t) {
        if (tid < BT) sX[tid] = gx;
        __syncthreads();   // sX ready; previous step's mma done reading sA

        if (t == 0) {
            // A[b, 4i+m] = bf16(s0[i] * x[b][m]); thread owns i = tid&127
            int i  = tid & 127;
            int bh = tid >> 7;
            float s = s0s[i];
            for (int b = bh * 32; b < bh * 32 + 32; ++b) {
                float4 x = sX[b];
                uint2 u;
                u.x = packbf(s * x.y, s * x.x);
                u.y = packbf(s * x.w, s * x.z);
                *reinterpret_cast<uint2*>(smem + OFF_A + ((b * PADK + 4 * i) << 1)) = u;
            }
        } else {
            // convert this warp's D fragments into A via bf16x2 HMUL2
#pragma unroll
            for (int mt = 0; mt < 2; ++mt) {
                int r = mg * 32 + mt * 16 + g;
                float4 xa = sX[r];
                float4 xb = sX[r + 8];
                uint32_t xa01 = packbf(xa.y, xa.x), xa23 = packbf(xa.w, xa.z);
                uint32_t xb01 = packbf(xb.y, xb.x), xb23 = packbf(xb.w, xb.z);
#pragma unroll
                for (int nt = 0; nt < 4; ++nt) {
                    int i0 = ng * 32 + nt * 8 + 2 * cc;
                    uint32_t s0p = packbf(acc[mt][nt][0], acc[mt][nt][0]);
                    uint32_t s1p = packbf(acc[mt][nt][1], acc[mt][nt][1]);
                    uint32_t s2p = packbf(acc[mt][nt][2], acc[mt][nt][2]);
                    uint32_t s3p = packbf(acc[mt][nt][3], acc[mt][nt][3]);
                    uint4 ua, ub;
                    ua.x = mulbf2(s0p, xa01); ua.y = mulbf2(s0p, xa23);
                    ua.z = mulbf2(s1p, xa01); ua.w = mulbf2(s1p, xa23);
                    *reinterpret_cast<uint4*>(smem + OFF_A + ((r * PADK + 4 * i0) << 1)) = ua;
                    ub.x = mulbf2(s2p, xb01); ub.y = mulbf2(s2p, xb23);
                    ub.z = mulbf2(s3p, xb01); ub.w = mulbf2(s3p, xb23);
                    *reinterpret_cast<uint4*>(smem + OFF_A + (((r + 8) * PADK + 4 * i0) << 1)) = ub;
                }
            }
        }
#pragma unroll
        for (int mt = 0; mt < 2; ++mt)
#pragma unroll
            for (int nt = 0; nt < 4; ++nt)
#pragma unroll
                for (int q = 0; q < 4; ++q) acc[mt][nt][q] = 0.f;
        __syncthreads();   // sA fully built

        // prefetch next step's x during the GEMM (off the critical path)
        if (tid < BT && t + 1 < T_DIV) gx = g_div4[(t + 1) * B_FULL + b0 + tid];

        // ---- GEMM: section 1 (kt < NB): B from registers, only A ldsm ----
        uint32_t Af[2][2][4], Bf[2][2][4];
        ldsm4(Af[0][0], aBase[0]);
        ldsm4(Af[0][1], aBase[1]);
        ldsm4(Bf[NB & 1][0], bBase[0] + NB * 32);   // preload B for kt=NB
        ldsm4(Bf[NB & 1][1], bBase[1] + NB * 32);
#pragma unroll
        for (int kt = 0; kt < NB; ++kt) {
            int cur = kt & 1, nx = cur ^ 1;
            ldsm4(Af[nx][0], aBase[0] + (kt + 1) * 32);
            ldsm4(Af[nx][1], aBase[1] + (kt + 1) * 32);
#pragma unroll
            for (int nt = 0; nt < 4; ++nt) {
                uint32_t b0v = Bp[kt][nt >> 1][(nt & 1) * 2];
                uint32_t b1v = Bp[kt][nt >> 1][(nt & 1) * 2 + 1];
                mma16816(acc[0][nt], Af[cur][0], b0v, b1v);
                mma16816(acc[1][nt], Af[cur][1], b0v, b1v);
            }
        }
        // ---- section 2 (kt = NB..31): double-buffered A and B ----
#pragma unroll
        for (int kt = NB; kt < 32; ++kt) {
            int cur = kt & 1, nx = cur ^ 1;
            if (kt < 31) {
                ldsm4(Af[nx][0], aBase[0] + (kt + 1) * 32);
                ldsm4(Af[nx][1], aBase[1] + (kt + 1) * 32);
                ldsm4(Bf[nx][0], bBase[0] + (kt + 1) * 32);
                ldsm4(Bf[nx][1], bBase[1] + (kt + 1) * 32);
            }
#pragma unroll
            for (int nt = 0; nt < 4; ++nt) {
                uint32_t b0v = Bf[cur][nt >> 1][(nt & 1) * 2];
                uint32_t b1v = Bf[cur][nt >> 1][(nt & 1) * 2 + 1];
                mma16816(acc[0][nt], Af[cur][0], b0v, b1v);
                mma16816(acc[1][nt], Af[cur][1], b0v, b1v);
            }
        }
    }

    // ---- final projection: logits[b] = dot(state_b, wl) ----
#pragma unroll
    for (int mt = 0; mt < 2; ++mt) {
        int r = mg * 32 + mt * 16 + g;
        float p0 = 0.f, p1 = 0.f;
#pragma unroll
        for (int nt = 0; nt < 4; ++nt) {
            int i0 = ng * 32 + nt * 8 + 2 * cc;
            float w0 = wls[i0], w1 = wls[i0 + 1];
            p0 += acc[mt][nt][0] * w0 + acc[mt][nt][1] * w1;
            p1 += acc[mt][nt][2] * w0 + acc[mt][nt][3] * w1;
        }
        sRed[r * 16 + ng * 4 + cc]       = p0;
        sRed[(r + 8) * 16 + ng * 4 + cc] = p1;
    }
    __syncthreads();
    if (tid < BT) {
        float sum = 0.f;
#pragma unroll
        for (int q = 0; q < 16; ++q) sum += sRed[tid * 16 + q];
        g_logits[(b0 + tid) * C_CLS + c] = sum;
    }
}

// ---------------------------------------------------------------------------
// Kernel 3: log_softmax over C=10
// ---------------------------------------------------------------------------
__global__ void lsm_kernel(float* __restrict__ out) {
    int b = blockIdx.x * blockDim.x + threadIdx.x;
    if (b >= B_FULL) return;
    float v[C_CLS];
    float mx = -INFINITY;
#pragma unroll
    for (int c = 0; c < C_CLS; ++c) {
        v[c] = g_logits[b * C_CLS + c];
        mx = fmaxf(mx, v[c]);
    }
    float s = 0.f;
#pragma unroll
    for (int c = 0; c < C_CLS; ++c) s += expf(v[c] - mx);
    float lg = mx + logf(s);
#pragma unroll
    for (int c = 0; c < C_CLS; ++c) out[b * C_CLS + c] = v[c] - lg;
}

// ---------------------------------------------------------------------------
// Entry point
// ---------------------------------------------------------------------------
extern "C" void kernel_launch(void* const* d_in, const int* in_sizes, int n_in,
                              void* d_out, int out_size) {
    const float* tensor  = (const float*)d_in[0];   // (2048, 1024)
    const float* w_first = (const float*)d_in[1];   // (10, 1, 4, 128)
    const float* w_mid   = (const float*)d_in[2];   // (10, 128, 4, 128)
    const float* w_last  = (const float*)d_in[3];   // (10, 128, 4, 1)
    float* out = (float*)d_out;                     // (2048, 10)

    cudaFuncSetAttribute(rec_hmma_kernel, cudaFuncAttributeMaxDynamicSharedMemorySize, SMEM_BYTES);

    feat_kernel<<<(B_FULL * T_DIV) / 256, 256>>>(tensor);
    rec_hmma_kernel<<<dim3(B_FULL / BT, C_CLS), NTHR, SMEM_BYTES>>>(w_first, w_mid, w_last);
    lsm_kernel<<<(B_FULL + 255) / 256, 256>>>(out);
}